// round 9
// baseline (speedup 1.0000x reference)
#include <cuda_runtime.h>
#include <cuda_bf16.h>
#include <cstdint>

// Problem constants
#define B    2
#define N    512
#define MV   512
#define DIN  256
#define H    16
#define DOUT 128
#define LN_EPS 1e-5f

__device__ float g_proj[B * N * 2 * H];            // 128 KB
__device__ float g_T[B * MV * H * DOUT];           // 8 MB

#define FMA_F32X2(d_, a_, b_, c_) \
    asm("fma.rn.f32x2 %0, %1, %2, %3;" : "=l"(d_) : "l"(a_), "l"(b_), "l"(c_))

#define DUP_F32X2(d_, f_) \
    asm("mov.b64 %0, {%1, %1};" : "=l"(d_) : "f"(f_))

#define STCS_V2U64(p_, x_, y_) \
    asm volatile("st.global.cs.v2.u64 [%0], {%1, %2};" \
                 :: "l"(p_), "l"(x_), "l"(y_) : "memory")

// ---------------------------------------------------------------------------
// k_pre v3: fused LayerNorm + proj + T, d-split for parallelism.
// Grid = 512 CTAs = (rowgroup rg = blk>>2) x (d-quad dq = blk&3), 256 thr.
// CTA handles rows rg*8..rg*8+7  x  d in [dq*32, dq*32+32).
//  - Wsm: CTA's 32-d slice of W_out transposed in smem (coalesced LDG,
//    pad-33 STS -> conflict-free LDS later).
//  - LN + proj recomputed per d-quad (wall-time free); dq==0 writes proj.
//  - Phase C: warp w owns p = {2w, 2w+1}; wq in regs; coalesced T stores.
// ---------------------------------------------------------------------------
__global__ __launch_bounds__(256) void k_pre(
    const float* __restrict__ feats, const float* __restrict__ gamma,
    const float* __restrict__ beta,  const float* __restrict__ W_in,
    const float* __restrict__ b_in,  const float* __restrict__ W_out,
    float* __restrict__ proj,        float* __restrict__ T)
{
    __shared__ __align__(16) float Wsm[256 * 33];   // 33.8 KB [pq][dl]
    __shared__ __align__(16) float xs[8][DIN];      // 8 KB
    __shared__ float bqs[8][16];

    int t    = threadIdx.x;
    int blk  = blockIdx.x;
    int dq   = blk & 3;
    int rg   = blk >> 2;
    int w    = t >> 5;
    int lane = t & 31;

    // ---- stage Wsm = W_out[dq*32 .. +31][0..255] transposed ----
    #pragma unroll
    for (int it = 0; it < 32; it++) {
        int idx = t + it * 256;            // 0..8191
        int pq  = idx & 255;
        int dl  = idx >> 8;                // 0..31
        Wsm[pq * 33 + dl] = W_out[(dq * 32 + dl) * 256 + pq];
    }

    // ---- Phase A: LN, warp per row ----
    int r = rg * 8 + w;                    // global row = b*N + n
    {
        const float4* f4 = (const float4*)(feats + (size_t)r * DIN);
        float4 va = f4[lane * 2], vb = f4[lane * 2 + 1];
        float s  = va.x + va.y + va.z + va.w + vb.x + vb.y + vb.z + vb.w;
        float s2 = va.x*va.x + va.y*va.y + va.z*va.z + va.w*va.w
                 + vb.x*vb.x + vb.y*vb.y + vb.z*vb.z + vb.w*vb.w;
        #pragma unroll
        for (int o = 16; o; o >>= 1) {
            s  += __shfl_xor_sync(0xFFFFFFFFu, s,  o);
            s2 += __shfl_xor_sync(0xFFFFFFFFu, s2, o);
        }
        float mu  = s  * (1.f / DIN);
        float var = s2 * (1.f / DIN) - mu * mu;
        float rs  = rsqrtf(var + LN_EPS);

        const float4* g4 = (const float4*)gamma;
        const float4* b4 = (const float4*)beta;
        float4 ga = g4[lane * 2], gb = g4[lane * 2 + 1];
        float4 ba = b4[lane * 2], bb = b4[lane * 2 + 1];
        float* xrow = xs[w] + lane * 8;
        xrow[0] = (va.x - mu) * rs * ga.x + ba.x;
        xrow[1] = (va.y - mu) * rs * ga.y + ba.y;
        xrow[2] = (va.z - mu) * rs * ga.z + ba.z;
        xrow[3] = (va.w - mu) * rs * ga.w + ba.w;
        xrow[4] = (vb.x - mu) * rs * gb.x + bb.x;
        xrow[5] = (vb.y - mu) * rs * gb.y + bb.y;
        xrow[6] = (vb.z - mu) * rs * gb.z + bb.z;
        xrow[7] = (vb.w - mu) * rs * gb.w + bb.w;
    }
    __syncwarp();

    // ---- Phase B: proj[row=w][col=lane]; W_in straight from L1 ----
    {
        const float* xr = xs[w];
        float a0 = 0.f, a1 = 0.f, a2 = 0.f, a3 = 0.f;
        #pragma unroll 8
        for (int i = 0; i < DIN; i += 4) {
            a0 = fmaf(xr[i],     __ldg(&W_in[(i)     * 32 + lane]), a0);
            a1 = fmaf(xr[i + 1], __ldg(&W_in[(i + 1) * 32 + lane]), a1);
            a2 = fmaf(xr[i + 2], __ldg(&W_in[(i + 2) * 32 + lane]), a2);
            a3 = fmaf(xr[i + 3], __ldg(&W_in[(i + 3) * 32 + lane]), a3);
        }
        float pv = b_in[lane] + ((a0 + a1) + (a2 + a3));
        if (dq == 0) proj[r * 32 + lane] = pv;
        if (lane >= 16) bqs[w][lane - 16] = pv;
    }
    __syncthreads();

    // ---- Phase C: T[row][p][d] = sum_q Wsm[p*16+q][lane] * bq[row][q] ----
    {
        int p0 = w * 2;                    // warp owns p0, p0+1
        float wq0[16], wq1[16];
        #pragma unroll
        for (int q = 0; q < 16; q++) {
            wq0[q] = Wsm[((p0 + 0) * 16 + q) * 33 + lane];
            wq1[q] = Wsm[((p0 + 1) * 16 + q) * 33 + lane];
        }
        int base_r = rg * 8;
        int d = dq * 32 + lane;
        #pragma unroll
        for (int mm = 0; mm < 8; mm++) {
            float acc0 = 0.f, acc1 = 0.f;
            #pragma unroll
            for (int q = 0; q < 16; q++) {
                float bv = bqs[mm][q];
                acc0 = fmaf(wq0[q], bv, acc0);
                acc1 = fmaf(wq1[q], bv, acc1);
            }
            size_t rb = (size_t)(base_r + mm) * H;
            T[(rb + p0)     * DOUT + d] = acc0;
            T[(rb + p0 + 1) * DOUT + d] = acc1;
        }
    }
}

// ---------------------------------------------------------------------------
// k_main v6.1 (unchanged): out[b,n,m,d] = b_out[d] + sum_p a[b,n,p]*T[b,m,p,d]
// Grid = B * M * 2 = 2048 CTAs, 256 threads (8 warps), occ 2.
// ---------------------------------------------------------------------------
__global__ __launch_bounds__(256, 2) void k_main(
    const float* __restrict__ proj, const float* __restrict__ Tg,
    const float* __restrict__ b_out, float* __restrict__ out)
{
    int b    = blockIdx.x >> 10;
    int m    = (blockIdx.x >> 1) & 511;
    int n0   = (blockIdx.x & 1) * 256;
    int t    = threadIdx.x;
    int w    = t >> 5;
    int lane = t & 31;

    __shared__ __align__(16) float Ts[H * DOUT];     // 8 KB  [p][d]
    __shared__ __align__(16) float As[256 * H];      // 16 KB [row][p]

    {
        const float4* Tsrc = (const float4*)(Tg + (size_t)(b * N + m) * (H * DOUT));
        float4* Td = (float4*)Ts;
        Td[t]       = Tsrc[t];
        Td[t + 256] = Tsrc[t + 256];
    }
    {
        const float4* psrc = (const float4*)(proj + (size_t)(b * N + n0) * 32);
        float4* Ad = (float4*)As;
        #pragma unroll
        for (int it = 0; it < 4; it++) {
            int idx = t + it * 256;
            int row = idx >> 2;
            int q4  = idx & 3;
            Ad[idx] = psrc[row * 8 + q4];
        }
    }
    __syncthreads();

    unsigned long long Tp[H][2];
    {
        const ulonglong2* TU = (const ulonglong2*)Ts;
        #pragma unroll
        for (int p = 0; p < H; p++) {
            ulonglong2 q = TU[p * 32 + lane];
            Tp[p][0] = q.x; Tp[p][1] = q.y;
        }
    }

    unsigned long long bo0, bo1;
    {
        const unsigned long long* bo = (const unsigned long long*)b_out;
        bo0 = bo[2 * lane]; bo1 = bo[2 * lane + 1];
    }

    size_t rowstride = (size_t)MV * DOUT;
    float* obase = out + (((size_t)(b * N) + n0 + w * 32) * MV + m) * DOUT
                       + lane * 4;

    #pragma unroll 1
    for (int jb = 0; jb < 32; jb += 4) {
        unsigned long long acc[4][2];
        #pragma unroll
        for (int j = 0; j < 4; j++) { acc[j][0] = bo0; acc[j][1] = bo1; }

        #pragma unroll
        for (int j = 0; j < 4; j++) {
            int row = w * 32 + jb + j;
            const float4* ar = (const float4*)(As + row * H);
            float4 A0 = ar[0], A1 = ar[1], A2 = ar[2], A3 = ar[3];
            float a16[16] = { A0.x,A0.y,A0.z,A0.w, A1.x,A1.y,A1.z,A1.w,
                              A2.x,A2.y,A2.z,A2.w, A3.x,A3.y,A3.z,A3.w };
            #pragma unroll
            for (int p = 0; p < H; p++) {
                unsigned long long ad;
                DUP_F32X2(ad, a16[p]);
                FMA_F32X2(acc[j][0], ad, Tp[p][0], acc[j][0]);
                FMA_F32X2(acc[j][1], ad, Tp[p][1], acc[j][1]);
            }
        }

        float* op = obase + (size_t)jb * rowstride;
        #pragma unroll
        for (int j = 0; j < 4; j++)
            STCS_V2U64(op + (size_t)j * rowstride, acc[j][0], acc[j][1]);
    }
}

// ---------------------------------------------------------------------------
extern "C" void kernel_launch(void* const* d_in, const int* in_sizes, int n_in,
                              void* d_out, int out_size)
{
    const float* feats  = (const float*)d_in[0];
    const float* gamma  = (const float*)d_in[1];
    const float* beta   = (const float*)d_in[2];
    const float* W_in   = (const float*)d_in[3];
    const float* b_in   = (const float*)d_in[4];
    const float* W_out  = (const float*)d_in[5];
    const float* b_out  = (const float*)d_in[6];
    float* out = (float*)d_out;

    float* proj; cudaGetSymbolAddress((void**)&proj, g_proj);
    float* T;    cudaGetSymbolAddress((void**)&T,    g_T);

    k_pre<<<512, 256>>>(feats, gamma, beta, W_in, b_in, W_out, proj, T);
    k_main<<<B * MV * 2, 256>>>(proj, T, b_out, out);
}

// round 10
// speedup vs baseline: 1.1061x; 1.1061x over previous
#include <cuda_runtime.h>
#include <cuda_bf16.h>
#include <cstdint>

// Problem constants
#define B    2
#define N    512
#define MV   512
#define DIN  256
#define H    16
#define DOUT 128
#define LN_EPS 1e-5f

__device__ float g_proj[B * N * 2 * H];            // 128 KB
__device__ float g_T[B * MV * H * DOUT];           // 8 MB
__device__ float g_Wt[256 * DOUT];                 // 128 KB, W_out^T [pq][d]

#define FMA_F32X2(d_, a_, b_, c_) \
    asm("fma.rn.f32x2 %0, %1, %2, %3;" : "=l"(d_) : "l"(a_), "l"(b_), "l"(c_))

#define DUP_F32X2(d_, f_) \
    asm("mov.b64 %0, {%1, %1};" : "=l"(d_) : "f"(f_))

#define STCS_V2U64(p_, x_, y_) \
    asm volatile("st.global.cs.v2.u64 [%0], {%1, %2};" \
                 :: "l"(p_), "l"(x_), "l"(y_) : "memory")

// ---------------------------------------------------------------------------
// k_wt v2: tiled transpose W_out [128 d][256 pq] -> Wt [256 pq][128 d].
// Grid = 32 CTAs (4 d-tiles x 8 pq-tiles), 256 threads.  Both sides coalesced.
// ---------------------------------------------------------------------------
__global__ __launch_bounds__(256) void k_wt(
    const float* __restrict__ W_out, float* __restrict__ Wt)
{
    __shared__ float sm[32][33];
    int d0  = (blockIdx.x & 3) * 32;      // d-tile origin
    int pq0 = (blockIdx.x >> 2) * 32;     // pq-tile origin
    int w    = threadIdx.x >> 5;
    int lane = threadIdx.x & 31;

    #pragma unroll
    for (int it = 0; it < 4; it++) {
        int r = w + it * 8;               // 0..31 (d within tile)
        sm[r][lane] = W_out[(d0 + r) * 256 + pq0 + lane];
    }
    __syncthreads();
    #pragma unroll
    for (int it = 0; it < 4; it++) {
        int r = w + it * 8;               // 0..31 (pq within tile)
        Wt[(pq0 + r) * DOUT + d0 + lane] = sm[lane][r];
    }
}

// ---------------------------------------------------------------------------
// k_pre v2 (R8 verbatim): fused LayerNorm + proj + T.  Grid 128 x 256.
// ---------------------------------------------------------------------------
__global__ __launch_bounds__(256) void k_pre(
    const float* __restrict__ feats, const float* __restrict__ gamma,
    const float* __restrict__ beta,  const float* __restrict__ W_in,
    const float* __restrict__ b_in,  const float* __restrict__ Wt,
    float* __restrict__ proj,        float* __restrict__ T)
{
    __shared__ __align__(16) float Wins[DIN * 32];   // 32 KB
    __shared__ __align__(16) float xs[8][DIN];       // 8 KB
    __shared__ float bqs[8][16];

    int t    = threadIdx.x;
    int blk  = blockIdx.x;
    int w    = t >> 5;
    int lane = t & 31;

    #pragma unroll
    for (int it = 0; it < 8; it++) {
        int idx = t + it * 256;
        ((float4*)Wins)[idx] = ((const float4*)W_in)[idx];
    }

    int r = blk * 8 + w;
    {
        const float4* f4 = (const float4*)(feats + (size_t)r * DIN);
        float4 va = f4[lane * 2], vb = f4[lane * 2 + 1];
        float s  = va.x + va.y + va.z + va.w + vb.x + vb.y + vb.z + vb.w;
        float s2 = va.x*va.x + va.y*va.y + va.z*va.z + va.w*va.w
                 + vb.x*vb.x + vb.y*vb.y + vb.z*vb.z + vb.w*vb.w;
        #pragma unroll
        for (int o = 16; o; o >>= 1) {
            s  += __shfl_xor_sync(0xFFFFFFFFu, s,  o);
            s2 += __shfl_xor_sync(0xFFFFFFFFu, s2, o);
        }
        float mu  = s  * (1.f / DIN);
        float var = s2 * (1.f / DIN) - mu * mu;
        float rs  = rsqrtf(var + LN_EPS);

        const float4* g4 = (const float4*)gamma;
        const float4* b4 = (const float4*)beta;
        float4 ga = g4[lane * 2], gb = g4[lane * 2 + 1];
        float4 ba = b4[lane * 2], bb = b4[lane * 2 + 1];
        float* xrow = xs[w] + lane * 8;
        xrow[0] = (va.x - mu) * rs * ga.x + ba.x;
        xrow[1] = (va.y - mu) * rs * ga.y + ba.y;
        xrow[2] = (va.z - mu) * rs * ga.z + ba.z;
        xrow[3] = (va.w - mu) * rs * ga.w + ba.w;
        xrow[4] = (vb.x - mu) * rs * gb.x + bb.x;
        xrow[5] = (vb.y - mu) * rs * gb.y + bb.y;
        xrow[6] = (vb.z - mu) * rs * gb.z + bb.z;
        xrow[7] = (vb.w - mu) * rs * gb.w + bb.w;
    }
    __syncthreads();

    {
        const float* xr = xs[w];
        float a0 = 0.f, a1 = 0.f, a2 = 0.f, a3 = 0.f;
        #pragma unroll
        for (int i = 0; i < DIN; i += 4) {
            a0 = fmaf(xr[i],     Wins[(i)     * 32 + lane], a0);
            a1 = fmaf(xr[i + 1], Wins[(i + 1) * 32 + lane], a1);
            a2 = fmaf(xr[i + 2], Wins[(i + 2) * 32 + lane], a2);
            a3 = fmaf(xr[i + 3], Wins[(i + 3) * 32 + lane], a3);
        }
        float pv = b_in[lane] + ((a0 + a1) + (a2 + a3));
        proj[r * 32 + lane] = pv;
        if (lane >= 16) bqs[w][lane - 16] = pv;
    }
    __syncthreads();

    {
        int d  = t & 127;
        int ph = t >> 7;
        int base_r = blk * 8;
        #pragma unroll
        for (int pi = 0; pi < 8; pi++) {
            int p = ph * 8 + pi;
            float wq[16];
            #pragma unroll
            for (int q = 0; q < 16; q++)
                wq[q] = Wt[(p * 16 + q) * DOUT + d];
            #pragma unroll
            for (int mm = 0; mm < 8; mm++) {
                float acc = 0.f;
                #pragma unroll
                for (int q = 0; q < 16; q++)
                    acc = fmaf(wq[q], bqs[mm][q], acc);
                T[((size_t)(base_r + mm) * H + p) * DOUT + d] = acc;
            }
        }
    }
}

// ---------------------------------------------------------------------------
// k_main v6 (R7 verbatim, grid 1024): out = b_out + sum_p a * T
// CTA = one (b,m), all 512 rows.  Warp = 64 rows.  T in 64 regs per thread.
// ---------------------------------------------------------------------------
__global__ __launch_bounds__(256, 2) void k_main(
    const float* __restrict__ proj, const float* __restrict__ Tg,
    const float* __restrict__ b_out, float* __restrict__ out)
{
    int b    = blockIdx.x >> 9;
    int m    = blockIdx.x & 511;
    int t    = threadIdx.x;
    int w    = t >> 5;              // warp -> rows w*64 .. w*64+63
    int lane = t & 31;              // chunk: d = lane*4 .. +3

    __shared__ __align__(16) float Ts[H * DOUT];   // 8 KB  [p][d]
    __shared__ __align__(16) float As[N * H];      // 32 KB [row][p]

    {
        const float4* Tsrc = (const float4*)(Tg + (size_t)(b * N + m) * (H * DOUT));
        float4* Td = (float4*)Ts;
        Td[t]       = Tsrc[t];
        Td[t + 256] = Tsrc[t + 256];
    }
    {
        const float4* psrc = (const float4*)(proj + (size_t)b * N * 32);
        float4* Ad = (float4*)As;
        #pragma unroll
        for (int it = 0; it < 8; it++) {
            int idx = t + it * 256;
            int row = idx >> 2;
            int q4  = idx & 3;
            Ad[idx] = psrc[row * 8 + q4];
        }
    }
    __syncthreads();

    unsigned long long Tp[H][2];
    {
        const ulonglong2* TU = (const ulonglong2*)Ts;
        #pragma unroll
        for (int p = 0; p < H; p++) {
            ulonglong2 q = TU[p * 32 + lane];
            Tp[p][0] = q.x; Tp[p][1] = q.y;
        }
    }

    unsigned long long bo0, bo1;
    {
        const unsigned long long* bo = (const unsigned long long*)b_out;
        bo0 = bo[2 * lane]; bo1 = bo[2 * lane + 1];
    }

    size_t rowstride = (size_t)MV * DOUT;
    float* obase = out + (((size_t)(b * N) + w * 64) * MV + m) * DOUT + lane * 4;

    #pragma unroll 1
    for (int jb = 0; jb < 64; jb += 4) {
        unsigned long long acc[4][2];
        #pragma unroll
        for (int j = 0; j < 4; j++) { acc[j][0] = bo0; acc[j][1] = bo1; }

        #pragma unroll
        for (int j = 0; j < 4; j++) {
            int row = w * 64 + jb + j;
            const float4* ar = (const float4*)(As + row * H);
            float4 A0 = ar[0], A1 = ar[1], A2 = ar[2], A3 = ar[3];
            float a16[16] = { A0.x,A0.y,A0.z,A0.w, A1.x,A1.y,A1.z,A1.w,
                              A2.x,A2.y,A2.z,A2.w, A3.x,A3.y,A3.z,A3.w };
            #pragma unroll
            for (int p = 0; p < H; p++) {
                unsigned long long ad;
                DUP_F32X2(ad, a16[p]);
                FMA_F32X2(acc[j][0], ad, Tp[p][0], acc[j][0]);
                FMA_F32X2(acc[j][1], ad, Tp[p][1], acc[j][1]);
            }
        }

        float* op = obase + (size_t)jb * rowstride;
        #pragma unroll
        for (int j = 0; j < 4; j++)
            STCS_V2U64(op + (size_t)j * rowstride, acc[j][0], acc[j][1]);
    }
}

// ---------------------------------------------------------------------------
extern "C" void kernel_launch(void* const* d_in, const int* in_sizes, int n_in,
                              void* d_out, int out_size)
{
    const float* feats  = (const float*)d_in[0];
    const float* gamma  = (const float*)d_in[1];
    const float* beta   = (const float*)d_in[2];
    const float* W_in   = (const float*)d_in[3];
    const float* b_in   = (const float*)d_in[4];
    const float* W_out  = (const float*)d_in[5];
    const float* b_out  = (const float*)d_in[6];
    float* out = (float*)d_out;

    float* proj; cudaGetSymbolAddress((void**)&proj, g_proj);
    float* T;    cudaGetSymbolAddress((void**)&T,    g_T);
    float* Wt;   cudaGetSymbolAddress((void**)&Wt,   g_Wt);

    k_wt<<<32, 256>>>(W_out, Wt);
    k_pre<<<(B * N) / 8, 256>>>(feats, gamma, beta, W_in, b_in, Wt, proj, T);
    k_main<<<B * MV, 256>>>(proj, T, b_out, out);
}